// round 4
// baseline (speedup 1.0000x reference)
#include <cuda_runtime.h>
#include <math.h>

#define BB 128
#define LL 196
#define DD 1024
#define LP1 197

// ---------------- scratch (__device__ globals; no allocations allowed) -------
__device__ float g_fr[BB * DD];
__device__ float g_ho[BB * DD];
__device__ float g_fr_e[BB * DD];
__device__ float g_ho_e[BB * DD];
__device__ float g_PI[BB * LP1];
__device__ float g_att[BB * DD];

__device__ __forceinline__ float fast_tanh(float x) {
    float y;
    asm("tanh.approx.f32 %0, %1;" : "=f"(y) : "f"(x));
    return y;
}

// ---------------- fp32 GEMM: Y[m,n] = act( sum_k X[m,k]*W[n,k] + bias[n] ) ---
// X: [128, 1024] row-major, W: [1024, 1024] row-major (out,in), Y: [128,1024]
// act: 0=none, 1=relu, 2=tanh(accurate)
#define GBM 32
#define GBN 64
#define GBK 16

__device__ __forceinline__ void gemm_tile(
    const float* __restrict__ X, const float* __restrict__ W,
    const float* __restrict__ bias, float* __restrict__ Y, int act)
{
    __shared__ float Xs[GBK][GBM + 1];   // +1 pad: conflict-free STS
    __shared__ float Ws[GBK][GBN + 4];   // +4 pad: keeps float4 alignment, 2-way STS

    const int tid  = threadIdx.x;        // 256 threads
    const int tx   = tid & 15;           // 16 col-groups * 4 cols
    const int ty   = tid >> 4;           // 16 row-groups * 2 rows
    const int brow = blockIdx.y * GBM;
    const int bcol = blockIdx.x * GBN;
    const int kk0  = tid & 15;
    const int rr0  = tid >> 4;

    float acc[2][4] = {};

    for (int k0 = 0; k0 < DD; k0 += GBK) {
#pragma unroll
        for (int i = 0; i < 2; i++) {
            int m = rr0 + 16 * i;
            Xs[kk0][m] = X[(brow + m) * DD + k0 + kk0];
        }
#pragma unroll
        for (int i = 0; i < 4; i++) {
            int n = rr0 + 16 * i;
            Ws[kk0][n] = W[(bcol + n) * DD + k0 + kk0];
        }
        __syncthreads();
#pragma unroll
        for (int kk = 0; kk < GBK; kk++) {
            float a0 = Xs[kk][ty * 2 + 0];
            float a1 = Xs[kk][ty * 2 + 1];
            float4 bv = *reinterpret_cast<const float4*>(&Ws[kk][tx * 4]);
            acc[0][0] = fmaf(a0, bv.x, acc[0][0]);
            acc[0][1] = fmaf(a0, bv.y, acc[0][1]);
            acc[0][2] = fmaf(a0, bv.z, acc[0][2]);
            acc[0][3] = fmaf(a0, bv.w, acc[0][3]);
            acc[1][0] = fmaf(a1, bv.x, acc[1][0]);
            acc[1][1] = fmaf(a1, bv.y, acc[1][1]);
            acc[1][2] = fmaf(a1, bv.z, acc[1][2]);
            acc[1][3] = fmaf(a1, bv.w, acc[1][3]);
        }
        __syncthreads();
    }

#pragma unroll
    for (int r = 0; r < 2; r++) {
        int m = brow + ty * 2 + r;
#pragma unroll
        for (int c = 0; c < 4; c++) {
            int n = bcol + tx * 4 + c;
            float v = acc[r][c] + bias[n];
            if (act == 1)      v = fmaxf(v, 0.0f);
            else if (act == 2) v = tanhf(v);
            Y[m * DD + n] = v;
        }
    }
}

__global__ void gemm2_kernel(
    const float* __restrict__ X0, const float* __restrict__ W0,
    const float* __restrict__ b0, float* __restrict__ Y0, int act0,
    const float* __restrict__ X1, const float* __restrict__ W1,
    const float* __restrict__ b1, float* __restrict__ Y1, int act1)
{
    if (blockIdx.z == 0) gemm_tile(X0, W0, b0, Y0, act0);
    else                 gemm_tile(X1, W1, b1, Y1, act1);
}

// ---------------- scores + softmax fused: one CTA per batch row --------------
// scores[b][l] = sum_d tanh(embed[b][l][d] + ho_e[b][d]) * W_a[d] + b_a
// embed l=0 -> fr_e[b], l>=1 -> conv_feat_embed[b][l-1]
__global__ void attn_kernel(const float* __restrict__ cfe,
                            const float* __restrict__ W_a,
                            const float* __restrict__ b_a)
{
    __shared__ float s_hoe[DD];
    __shared__ float s_wa[DD];
    __shared__ float s_sc[LP1];
    __shared__ float s_red[8];

    const int b   = blockIdx.x;
    const int tid = threadIdx.x;   // 256

    for (int i = tid; i < DD; i += 256) {
        s_hoe[i] = g_ho_e[b * DD + i];
        s_wa[i]  = W_a[i];
    }
    __syncthreads();

    const int warp = tid >> 5;
    const int lane = tid & 31;

    for (int l = warp; l < LP1; l += 8) {
        const float* ebase = (l == 0) ? (g_fr_e + (size_t)b * DD)
                                      : (cfe + ((size_t)b * LL + (l - 1)) * (size_t)DD);
        float acc = 0.0f;
#pragma unroll 8
        for (int d = lane; d < DD; d += 32)
            acc = fmaf(fast_tanh(ebase[d] + s_hoe[d]), s_wa[d], acc);
#pragma unroll
        for (int off = 16; off > 0; off >>= 1)
            acc += __shfl_down_sync(0xffffffffu, acc, off);
        if (lane == 0) s_sc[l] = acc + b_a[0];
    }
    __syncthreads();

    // softmax over 197 scores (in smem)
    float v = (tid < LP1) ? s_sc[tid] : -1e30f;
    float m = v;
#pragma unroll
    for (int off = 16; off > 0; off >>= 1)
        m = fmaxf(m, __shfl_xor_sync(0xffffffffu, m, off));
    if (lane == 0) s_red[warp] = m;
    __syncthreads();
    if (tid == 0) {
        float mm = s_red[0];
#pragma unroll
        for (int i = 1; i < 8; i++) mm = fmaxf(mm, s_red[i]);
        s_red[0] = mm;
    }
    __syncthreads();
    const float mx = s_red[0];
    float pv = (tid < LP1) ? expf(v - mx) : 0.0f;
    float ssum = pv;
#pragma unroll
    for (int off = 16; off > 0; off >>= 1)
        ssum += __shfl_xor_sync(0xffffffffu, ssum, off);
    __syncthreads();                     // protect s_red reuse
    if (lane == 0) s_red[warp] = ssum;
    __syncthreads();
    if (tid == 0) {
        float t = 0.0f;
#pragma unroll
        for (int i = 0; i < 8; i++) t += s_red[i];
        s_red[0] = t;
    }
    __syncthreads();
    const float inv = 1.0f / s_red[0];
    if (tid < LP1) g_PI[b * LP1 + tid] = pv * inv;
}

// ---------------- weighted sum + residual: atten_out = visAtt + ho -----------
__global__ void wsum_kernel(const float* __restrict__ conv_feat)
{
    __shared__ float s_pi[LP1];
    const int b = blockIdx.y;
    const int d = blockIdx.x * 256 + threadIdx.x;

    for (int i = threadIdx.x; i < LP1; i += 256)
        s_pi[i] = g_PI[b * LP1 + i];
    __syncthreads();

    float acc = fmaf(s_pi[0], g_fr[b * DD + d], g_ho[b * DD + d]);
    const float* cf = conv_feat + (size_t)b * LL * DD + d;
#pragma unroll 4
    for (int l = 0; l < LL; l++)
        acc = fmaf(s_pi[l + 1], cf[(size_t)l * DD], acc);
    g_att[b * DD + d] = acc;
}

// ---------------- launch -----------------------------------------------------
extern "C" void kernel_launch(void* const* d_in, const int* in_sizes, int n_in,
                              void* d_out, int out_size)
{
    const float* h_out       = (const float*)d_in[0];
    const float* fake_region = (const float*)d_in[1];
    const float* conv_feat   = (const float*)d_in[2];
    const float* conv_embed  = (const float*)d_in[3];
    const float* W_fr  = (const float*)d_in[4];
    const float* b_fr  = (const float*)d_in[5];
    const float* W_fre = (const float*)d_in[6];
    const float* b_fre = (const float*)d_in[7];
    const float* W_ho  = (const float*)d_in[8];
    const float* b_ho  = (const float*)d_in[9];
    const float* W_hoe = (const float*)d_in[10];
    const float* b_hoe = (const float*)d_in[11];
    const float* W_a   = (const float*)d_in[12];
    const float* b_a   = (const float*)d_in[13];
    const float* W_h   = (const float*)d_in[14];
    const float* b_h   = (const float*)d_in[15];
    float* out = (float*)d_out;

    float *p_fr, *p_ho, *p_fr_e, *p_ho_e, *p_att;
    cudaGetSymbolAddress((void**)&p_fr,   g_fr);
    cudaGetSymbolAddress((void**)&p_ho,   g_ho);
    cudaGetSymbolAddress((void**)&p_fr_e, g_fr_e);
    cudaGetSymbolAddress((void**)&p_ho_e, g_ho_e);
    cudaGetSymbolAddress((void**)&p_att,  g_att);

    const dim3 ggrid2(DD / GBN, BB / GBM, 2);   // 16 x 4 x 2 = 128 CTAs
    const dim3 ggrid1(DD / GBN, BB / GBM, 1);   // 64 CTAs

    // stage 1: fr = relu(fake_region@W_fr^T+b), ho = tanh(h_out@W_ho^T+b)
    gemm2_kernel<<<ggrid2, 256>>>(fake_region, W_fr, b_fr, p_fr, 1,
                                  h_out,       W_ho, b_ho, p_ho, 2);
    // stage 2: fr_e = fr@W_fre^T+b, ho_e = ho@W_hoe^T+b
    gemm2_kernel<<<ggrid2, 256>>>(p_fr, W_fre, b_fre, p_fr_e, 0,
                                  p_ho, W_hoe, b_hoe, p_ho_e, 0);
    // scores + softmax (fused), one CTA per batch row
    attn_kernel<<<BB, 256>>>(conv_embed, W_a, b_a);
    // visAtt + ho
    wsum_kernel<<<dim3(DD / 256, BB), 256>>>(conv_feat);
    // final: h = tanh(atten_out@W_h^T + b_h)
    gemm2_kernel<<<ggrid1, 256>>>(p_att, W_h, b_h, out, 2,
                                  p_att, W_h, b_h, out, 2);
}

// round 6
// speedup vs baseline: 2.4978x; 2.4978x over previous
#include <cuda_runtime.h>
#include <math.h>

#define BB 128
#define LL 196
#define DD 1024
#define LP1 197

#define BN 64
#define BK 32
#define SPLITK 4
#define XS 36            // smem row stride (floats): (36*g+t) mod 32 = 4g+t -> conflict-free

// ---------------- scratch (__device__ globals; no allocations allowed) -------
__device__ float g_fr[BB * DD];
__device__ float g_ho[BB * DD];
__device__ float g_fr_e[BB * DD];
__device__ float g_ho_e[BB * DD];
__device__ float g_scores[BB * LP1];
__device__ float g_PI[BB * LP1];
__device__ float g_att[BB * DD];
__device__ float g_part[2][SPLITK][BB * DD];   // split-K partial sums

__device__ __forceinline__ float fast_tanh(float x) {
    float y;
    asm("tanh.approx.f32 %0, %1;" : "=f"(y) : "f"(x));
    return y;
}

__device__ __forceinline__ void tf32split(float x, float& hi, float& lo) {
    unsigned uh, ul;
    asm("cvt.rna.tf32.f32 %0, %1;" : "=r"(uh) : "f"(x));
    hi = __uint_as_float(uh);
    float r = x - hi;
    asm("cvt.rna.tf32.f32 %0, %1;" : "=r"(ul) : "f"(r));
    lo = __uint_as_float(ul);
}

__device__ __forceinline__ void mma8(float d[4],
                                     float a0, float a1, float a2, float a3,
                                     float b0, float b1) {
    asm volatile(
        "mma.sync.aligned.m16n8k8.row.col.f32.tf32.tf32.f32 "
        "{%0,%1,%2,%3},{%4,%5,%6,%7},{%8,%9},{%0,%1,%2,%3};"
        : "+f"(d[0]), "+f"(d[1]), "+f"(d[2]), "+f"(d[3])
        : "r"(__float_as_uint(a0)), "r"(__float_as_uint(a1)),
          "r"(__float_as_uint(a2)), "r"(__float_as_uint(a3)),
          "r"(__float_as_uint(b0)), "r"(__float_as_uint(b1)));
}

// ---------------- tf32 tensor-core GEMM, split-K, dual-problem via blockIdx.z
// C_partial[m,n] = sum_{k in split} X[m,k] * W[n,k]   (3xTF32 compensated)
// X: [128,1024], W: [1024,1024] row-major (out,in). BM=128 covers all of M.
__global__ void __launch_bounds__(256, 1) gemm_tf32_kernel(
    const float* __restrict__ X0, const float* __restrict__ W0,
    const float* __restrict__ X1, const float* __restrict__ W1)
{
    __shared__ float Xh[BB * XS];      // A hi (tf32-valued fp32), [m][k] stride 36
    __shared__ float Xl[BB * XS];      // A lo
    __shared__ float Wf[BN * XS];      // B fp32, [n][k] stride 36

    const int z  = blockIdx.z;
    const float* __restrict__ X = z ? X1 : X0;
    const float* __restrict__ W = z ? W1 : W0;
    const int nb = blockIdx.x;                 // 0..15
    const int sk = blockIdx.y;                 // 0..SPLITK-1
    const int kbase = sk * (DD / SPLITK);      // 256-wide k range

    const int tid  = threadIdx.x;
    const int lane = tid & 31;
    const int w    = tid >> 5;
    const int g    = lane >> 2;
    const int t    = lane & 3;
    const int wm   = (w & 3) * 32;             // warp tile: 32 rows
    const int wn   = (w >> 2) * 32;            // 32 cols

    float acc[2][4][4];
#pragma unroll
    for (int i = 0; i < 2; i++)
#pragma unroll
        for (int j = 0; j < 4; j++)
#pragma unroll
            for (int r = 0; r < 4; r++) acc[i][j][r] = 0.0f;

    for (int it = 0; it < (DD / SPLITK) / BK; ++it) {   // 8 iters
        const int k0 = kbase + it * BK;

        // X tile 128x32 -> hi/lo smem. thread: row=tid>>1, half=(tid&1)*16
        {
            const int row  = tid >> 1;
            const int half = (tid & 1) * 16;
            const float4* src = reinterpret_cast<const float4*>(X + row * DD + k0 + half);
#pragma unroll
            for (int j = 0; j < 4; ++j) {
                float4 v = src[j];
                float4 h, l;
                tf32split(v.x, h.x, l.x); tf32split(v.y, h.y, l.y);
                tf32split(v.z, h.z, l.z); tf32split(v.w, h.w, l.w);
                *reinterpret_cast<float4*>(&Xh[row * XS + half + 4 * j]) = h;
                *reinterpret_cast<float4*>(&Xl[row * XS + half + 4 * j]) = l;
            }
        }
        // W tile 64x32 fp32 smem
        {
#pragma unroll
            for (int j = 0; j < 2; ++j) {
                int u   = tid + 256 * j;
                int row = u >> 3;
                int c4  = (u & 7) * 4;
                float4 v = *reinterpret_cast<const float4*>(W + ((size_t)(nb * BN + row)) * DD + k0 + c4);
                *reinterpret_cast<float4*>(&Wf[row * XS + c4]) = v;
            }
        }
        __syncthreads();

#pragma unroll
        for (int kk = 0; kk < 4; ++kk) {
            const int ko = 8 * kk;
            // A fragments (hi+lo) for 2 m-atoms
            float ah[2][4], al[2][4];
#pragma unroll
            for (int i = 0; i < 2; ++i) {
                int m = wm + 16 * i;
                ah[i][0] = Xh[(m + g)     * XS + ko + t];
                ah[i][1] = Xh[(m + g + 8) * XS + ko + t];
                ah[i][2] = Xh[(m + g)     * XS + ko + t + 4];
                ah[i][3] = Xh[(m + g + 8) * XS + ko + t + 4];
                al[i][0] = Xl[(m + g)     * XS + ko + t];
                al[i][1] = Xl[(m + g + 8) * XS + ko + t];
                al[i][2] = Xl[(m + g)     * XS + ko + t + 4];
                al[i][3] = Xl[(m + g + 8) * XS + ko + t + 4];
            }
            // B fragments: load fp32, split in regs
            float bh[4][2], bl[4][2];
#pragma unroll
            for (int j = 0; j < 4; ++j) {
                int n = wn + 8 * j;
                float x0 = Wf[(n + g) * XS + ko + t];
                float x1 = Wf[(n + g) * XS + ko + t + 4];
                tf32split(x0, bh[j][0], bl[j][0]);
                tf32split(x1, bh[j][1], bl[j][1]);
            }
#pragma unroll
            for (int i = 0; i < 2; ++i)
#pragma unroll
                for (int j = 0; j < 4; ++j) {
                    mma8(acc[i][j], ah[i][0], ah[i][1], ah[i][2], ah[i][3], bl[j][0], bl[j][1]);
                    mma8(acc[i][j], al[i][0], al[i][1], al[i][2], al[i][3], bh[j][0], bh[j][1]);
                    mma8(acc[i][j], ah[i][0], ah[i][1], ah[i][2], ah[i][3], bh[j][0], bh[j][1]);
                }
        }
        __syncthreads();
    }

    // store partials: c0,c1 -> [m][2t,2t+1], c2,c3 -> [m+8][...]
    float* out = &g_part[z][sk][0];
#pragma unroll
    for (int i = 0; i < 2; ++i) {
#pragma unroll
        for (int j = 0; j < 4; ++j) {
            int m = wm + 16 * i + g;
            int n = nb * BN + wn + 8 * j + 2 * t;
            float2 v01 = make_float2(acc[i][j][0], acc[i][j][1]);
            float2 v23 = make_float2(acc[i][j][2], acc[i][j][3]);
            *reinterpret_cast<float2*>(&out[m * DD + n])       = v01;
            *reinterpret_cast<float2*>(&out[(m + 8) * DD + n]) = v23;
        }
    }
}

// ---------------- epilogue: sum split-K partials + bias + activation ---------
__global__ void epi_kernel(float* __restrict__ Y0, const float* __restrict__ b0, int act0,
                           float* __restrict__ Y1, const float* __restrict__ b1, int act1)
{
    const int z = blockIdx.y;
    float* Y = z ? Y1 : Y0;
    const float* bias = z ? b1 : b0;
    const int act = z ? act1 : act0;
    const int idx = blockIdx.x * 256 + threadIdx.x;
    float s = g_part[z][0][idx] + g_part[z][1][idx] + g_part[z][2][idx] + g_part[z][3][idx];
    s += bias[idx & (DD - 1)];
    if (act == 1)      s = fmaxf(s, 0.0f);
    else if (act == 2) s = tanhf(s);
    Y[idx] = s;
}

// ---------------- scores: one warp per l, grid (B, 25) ----------------------
__global__ void __launch_bounds__(256) score_kernel(const float* __restrict__ cfe,
                                                    const float* __restrict__ W_a,
                                                    const float* __restrict__ b_a)
{
    __shared__ __align__(16) float s_hoe[DD];
    __shared__ __align__(16) float s_wa[DD];

    const int b   = blockIdx.x;
    const int tid = threadIdx.x;
    for (int i = tid; i < DD; i += 256) {
        s_hoe[i] = g_ho_e[b * DD + i];
        s_wa[i]  = W_a[i];
    }
    __syncthreads();

    const int warp = tid >> 5;
    const int lane = tid & 31;
    const int l = blockIdx.y * 8 + warp;
    if (l >= LP1) return;

    const float* ebase = (l == 0) ? (g_fr_e + (size_t)b * DD)
                                  : (cfe + ((size_t)b * LL + (l - 1)) * (size_t)DD);
    float acc = 0.0f;
#pragma unroll
    for (int i = 0; i < 8; ++i) {
        int d = i * 128 + lane * 4;
        float4 e = *reinterpret_cast<const float4*>(ebase + d);
        float4 h = *reinterpret_cast<const float4*>(&s_hoe[d]);
        float4 a = *reinterpret_cast<const float4*>(&s_wa[d]);
        acc = fmaf(fast_tanh(e.x + h.x), a.x, acc);
        acc = fmaf(fast_tanh(e.y + h.y), a.y, acc);
        acc = fmaf(fast_tanh(e.z + h.z), a.z, acc);
        acc = fmaf(fast_tanh(e.w + h.w), a.w, acc);
    }
#pragma unroll
    for (int off = 16; off > 0; off >>= 1)
        acc += __shfl_down_sync(0xffffffffu, acc, off);
    if (lane == 0) g_scores[b * LP1 + l] = acc + b_a[0];
}

// ---------------- softmax over 197 scores, one CTA per b ---------------------
__global__ void softmax_kernel()
{
    __shared__ float s_red[8];
    const int b   = blockIdx.x;
    const int tid = threadIdx.x;
    const int warp = tid >> 5, lane = tid & 31;

    float v = (tid < LP1) ? g_scores[b * LP1 + tid] : -1e30f;
    float m = v;
#pragma unroll
    for (int off = 16; off > 0; off >>= 1)
        m = fmaxf(m, __shfl_xor_sync(0xffffffffu, m, off));
    if (lane == 0) s_red[warp] = m;
    __syncthreads();
    if (tid == 0) {
        float mm = s_red[0];
#pragma unroll
        for (int i = 1; i < 8; i++) mm = fmaxf(mm, s_red[i]);
        s_red[0] = mm;
    }
    __syncthreads();
    const float mx = s_red[0];
    float pv = (tid < LP1) ? expf(v - mx) : 0.0f;
    float ssum = pv;
#pragma unroll
    for (int off = 16; off > 0; off >>= 1)
        ssum += __shfl_xor_sync(0xffffffffu, ssum, off);
    __syncthreads();
    if (lane == 0) s_red[warp] = ssum;
    __syncthreads();
    if (tid == 0) {
        float tsum = 0.0f;
#pragma unroll
        for (int i = 0; i < 8; i++) tsum += s_red[i];
        s_red[0] = tsum;
    }
    __syncthreads();
    const float inv = 1.0f / s_red[0];
    if (tid < LP1) g_PI[b * LP1 + tid] = pv * inv;
}

// ---------------- weighted sum + residual, float4 per thread -----------------
__global__ void __launch_bounds__(128) wsum_kernel(const float* __restrict__ conv_feat)
{
    __shared__ float s_pi[LP1];
    const int b = blockIdx.y;
    const int d = blockIdx.x * 512 + threadIdx.x * 4;

    for (int i = threadIdx.x; i < LP1; i += 128)
        s_pi[i] = g_PI[b * LP1 + i];
    __syncthreads();

    const float p0 = s_pi[0];
    float4 fr4 = *reinterpret_cast<const float4*>(&g_fr[b * DD + d]);
    float4 ho4 = *reinterpret_cast<const float4*>(&g_ho[b * DD + d]);
    float4 acc;
    acc.x = fmaf(p0, fr4.x, ho4.x);
    acc.y = fmaf(p0, fr4.y, ho4.y);
    acc.z = fmaf(p0, fr4.z, ho4.z);
    acc.w = fmaf(p0, fr4.w, ho4.w);

    const float* cf = conv_feat + (size_t)b * LL * DD + d;
#pragma unroll 8
    for (int l = 0; l < LL; ++l) {
        float4 v = *reinterpret_cast<const float4*>(cf + (size_t)l * DD);
        float p = s_pi[l + 1];
        acc.x = fmaf(p, v.x, acc.x);
        acc.y = fmaf(p, v.y, acc.y);
        acc.z = fmaf(p, v.z, acc.z);
        acc.w = fmaf(p, v.w, acc.w);
    }
    *reinterpret_cast<float4*>(&g_att[b * DD + d]) = acc;
}

// ---------------- launch -----------------------------------------------------
extern "C" void kernel_launch(void* const* d_in, const int* in_sizes, int n_in,
                              void* d_out, int out_size)
{
    const float* h_out       = (const float*)d_in[0];
    const float* fake_region = (const float*)d_in[1];
    const float* conv_feat   = (const float*)d_in[2];
    const float* conv_embed  = (const float*)d_in[3];
    const float* W_fr  = (const float*)d_in[4];
    const float* b_fr  = (const float*)d_in[5];
    const float* W_fre = (const float*)d_in[6];
    const float* b_fre = (const float*)d_in[7];
    const float* W_ho  = (const float*)d_in[8];
    const float* b_ho  = (const float*)d_in[9];
    const float* W_hoe = (const float*)d_in[10];
    const float* b_hoe = (const float*)d_in[11];
    const float* W_a   = (const float*)d_in[12];
    const float* b_a   = (const float*)d_in[13];
    const float* W_h   = (const float*)d_in[14];
    const float* b_h   = (const float*)d_in[15];
    float* out = (float*)d_out;

    float *p_fr, *p_ho, *p_fr_e, *p_ho_e, *p_att;
    cudaGetSymbolAddress((void**)&p_fr,   g_fr);
    cudaGetSymbolAddress((void**)&p_ho,   g_ho);
    cudaGetSymbolAddress((void**)&p_fr_e, g_fr_e);
    cudaGetSymbolAddress((void**)&p_ho_e, g_ho_e);
    cudaGetSymbolAddress((void**)&p_att,  g_att);

    const dim3 gg2(DD / BN, SPLITK, 2);     // 16 x 4 x 2 = 128 CTAs
    const dim3 gg1(DD / BN, SPLITK, 1);
    const dim3 ge2(BB * DD / 256, 2);       // 512 x 2
    const dim3 ge1(BB * DD / 256, 1);

    // stage 1: fr = relu(fake_region@W_fr^T+b), ho = tanh(h_out@W_ho^T+b)
    gemm_tf32_kernel<<<gg2, 256>>>(fake_region, W_fr, h_out, W_ho);
    epi_kernel<<<ge2, 256>>>(p_fr, b_fr, 1, p_ho, b_ho, 2);
    // stage 2: fr_e, ho_e (no activation)
    gemm_tf32_kernel<<<gg2, 256>>>(p_fr, W_fre, p_ho, W_hoe);
    epi_kernel<<<ge2, 256>>>(p_fr_e, b_fre, 0, p_ho_e, b_hoe, 0);
    // attention scores + softmax
    score_kernel<<<dim3(BB, 25), 256>>>(conv_embed, W_a, b_a);
    softmax_kernel<<<BB, 256>>>();
    // visAtt + ho
    wsum_kernel<<<dim3(2, BB), 128>>>(conv_feat);
    // stage 3: h = tanh(att@W_h^T + b_h)
    gemm_tf32_kernel<<<gg1, 256>>>(p_att, W_h, p_att, W_h);
    epi_kernel<<<ge1, 256>>>(out, b_h, 2, out, b_h, 2);
}

// round 8
// speedup vs baseline: 3.3883x; 1.3565x over previous
#include <cuda_runtime.h>
#include <math.h>

#define BB 128
#define LL 196
#define DD 1024
#define LP1 197

#define GBM 64
#define GBN 64
#define GBK 32
#define SPLITK 4
#define XS 36            // smem row stride: (36*g+t) mod 32 = 4g+t -> conflict-free
#define WSPL 2           // wsum L-split
#define WCH (LL / WSPL)  // 98

// ---------------- scratch (__device__ globals; no allocations allowed) -------
__device__ float g_fr[BB * DD];
__device__ float g_ho[BB * DD];
__device__ float g_fr_e[BB * DD];
__device__ float g_ho_e[BB * DD];
__device__ float g_scores[BB * LP1];
__device__ float g_PI[BB * LP1];
__device__ float g_att[BB * DD];
__device__ float g_part[2][SPLITK][BB * DD];   // GEMM split-K partials
__device__ float g_wpart[WSPL][BB * DD];       // wsum split-L partials

__device__ __forceinline__ float fast_tanh(float x) {
    float y;
    asm("tanh.approx.f32 %0, %1;" : "=f"(y) : "f"(x));
    return y;
}

__device__ __forceinline__ float tf32hi(float x) {
    unsigned u;
    asm("cvt.rna.tf32.f32 %0, %1;" : "=r"(u) : "f"(x));
    return __uint_as_float(u);
}

__device__ __forceinline__ void tf32split(float x, float& hi, float& lo) {
    hi = tf32hi(x);
    lo = tf32hi(x - hi);
}

__device__ __forceinline__ void mma8(float d[4],
                                     float a0, float a1, float a2, float a3,
                                     float b0, float b1) {
    asm volatile(
        "mma.sync.aligned.m16n8k8.row.col.f32.tf32.tf32.f32 "
        "{%0,%1,%2,%3},{%4,%5,%6,%7},{%8,%9},{%0,%1,%2,%3};"
        : "+f"(d[0]), "+f"(d[1]), "+f"(d[2]), "+f"(d[3])
        : "r"(__float_as_uint(a0)), "r"(__float_as_uint(a1)),
          "r"(__float_as_uint(a2)), "r"(__float_as_uint(a3)),
          "r"(__float_as_uint(b0)), "r"(__float_as_uint(b1)));
}

// ---------------- tf32 tensor-core GEMM, split-K, pipelined ------------------
// partial[m,n] = sum_{k chunk} X[m,k]*W[n,k].  A = tf32(X), B split hi/lo.
// grid: (16 n-blocks, 2 m-blocks x 4 splitK, 2 problems), 256 threads.
__global__ void __launch_bounds__(256, 2) gemm_tf32_kernel(
    const float* __restrict__ X0, const float* __restrict__ W0,
    const float* __restrict__ X1, const float* __restrict__ W1)
{
    __shared__ float Xh[GBM * XS];
    __shared__ float Wf[GBN * XS];

    const int z  = blockIdx.z;
    const float* __restrict__ X = z ? X1 : X0;
    const float* __restrict__ W = z ? W1 : W0;
    const int nb = blockIdx.x;
    const int mb = blockIdx.y & 1;
    const int sk = blockIdx.y >> 1;
    const int kbase = sk * (DD / SPLITK);      // 256-wide K chunk, 8 iters

    const int tid  = threadIdx.x;
    const int lane = tid & 31;
    const int w    = tid >> 5;
    const int g    = lane >> 2;
    const int t    = lane & 3;
    const int wm   = (w & 3) * 16;             // 4 warps x 16 rows
    const int wn   = (w >> 2) * 32;            // 2 warps x 32 cols

    // loader: 64 rows x 32 cols = 512 float4, 2 per thread
    const int lr0 = tid >> 3;                  // rows 0..31
    const int lc4 = (tid & 7) * 4;
    const float* Xg = X + (size_t)(mb * GBM) * DD;
    const float* Wg = W + (size_t)(nb * GBN) * DD;

    float acc[4][4];
#pragma unroll
    for (int j = 0; j < 4; j++)
#pragma unroll
        for (int r = 0; r < 4; r++) acc[j][r] = 0.0f;

    // prologue: load iter 0 into smem
    {
        const int k0 = kbase;
#pragma unroll
        for (int j = 0; j < 2; ++j) {
            int row = lr0 + 32 * j;
            float4 xv = *reinterpret_cast<const float4*>(Xg + (size_t)row * DD + k0 + lc4);
            float4 wv = *reinterpret_cast<const float4*>(Wg + (size_t)row * DD + k0 + lc4);
            float4 h;
            h.x = tf32hi(xv.x); h.y = tf32hi(xv.y); h.z = tf32hi(xv.z); h.w = tf32hi(xv.w);
            *reinterpret_cast<float4*>(&Xh[row * XS + lc4]) = h;
            *reinterpret_cast<float4*>(&Wf[row * XS + lc4]) = wv;
        }
    }
    __syncthreads();

    for (int it = 0; it < 8; ++it) {
        float4 xr[2], wr[2];
        if (it < 7) {
            const int k0 = kbase + (it + 1) * GBK;
#pragma unroll
            for (int j = 0; j < 2; ++j) {
                int row = lr0 + 32 * j;
                xr[j] = *reinterpret_cast<const float4*>(Xg + (size_t)row * DD + k0 + lc4);
                wr[j] = *reinterpret_cast<const float4*>(Wg + (size_t)row * DD + k0 + lc4);
            }
        }

#pragma unroll
        for (int kk = 0; kk < 4; ++kk) {
            const int ko = 8 * kk;
            float a0 = Xh[(wm + g)     * XS + ko + t];
            float a1 = Xh[(wm + g + 8) * XS + ko + t];
            float a2 = Xh[(wm + g)     * XS + ko + t + 4];
            float a3 = Xh[(wm + g + 8) * XS + ko + t + 4];
#pragma unroll
            for (int j = 0; j < 4; ++j) {
                int n = wn + 8 * j;
                float x0 = Wf[(n + g) * XS + ko + t];
                float x1 = Wf[(n + g) * XS + ko + t + 4];
                float bh0, bl0, bh1, bl1;
                tf32split(x0, bh0, bl0);
                tf32split(x1, bh1, bl1);
                mma8(acc[j], a0, a1, a2, a3, bl0, bl1);
                mma8(acc[j], a0, a1, a2, a3, bh0, bh1);
            }
        }
        __syncthreads();

        if (it < 7) {
#pragma unroll
            for (int j = 0; j < 2; ++j) {
                int row = lr0 + 32 * j;
                float4 h;
                h.x = tf32hi(xr[j].x); h.y = tf32hi(xr[j].y);
                h.z = tf32hi(xr[j].z); h.w = tf32hi(xr[j].w);
                *reinterpret_cast<float4*>(&Xh[row * XS + lc4]) = h;
                *reinterpret_cast<float4*>(&Wf[row * XS + lc4]) = wr[j];
            }
            __syncthreads();
        }
    }

    // store partials: c0,c1 -> [m][2t,2t+1], c2,c3 -> [m+8][...]
    float* out = &g_part[z][sk][0];
    const int mrow = mb * GBM + wm + g;
#pragma unroll
    for (int j = 0; j < 4; ++j) {
        int n = nb * GBN + wn + 8 * j + 2 * t;
        *reinterpret_cast<float2*>(&out[(size_t)mrow * DD + n])       = make_float2(acc[j][0], acc[j][1]);
        *reinterpret_cast<float2*>(&out[(size_t)(mrow + 8) * DD + n]) = make_float2(acc[j][2], acc[j][3]);
    }
}

// ---------------- epilogue: sum split-K partials + bias + act (float4) -------
__global__ void __launch_bounds__(256) epi_kernel(
    float* __restrict__ Y0, const float* __restrict__ b0, int act0,
    float* __restrict__ Y1, const float* __restrict__ b1, int act1)
{
    const int z = blockIdx.y;
    float* Y = z ? Y1 : Y0;
    const float* bias = z ? b1 : b0;
    const int act = z ? act1 : act0;
    const int i4 = (blockIdx.x * 256 + threadIdx.x) * 4;

    float4 s = *reinterpret_cast<const float4*>(&g_part[z][0][i4]);
#pragma unroll
    for (int p = 1; p < SPLITK; ++p) {
        float4 v = *reinterpret_cast<const float4*>(&g_part[z][p][i4]);
        s.x += v.x; s.y += v.y; s.z += v.z; s.w += v.w;
    }
    float4 bv = *reinterpret_cast<const float4*>(&bias[i4 & (DD - 1)]);
    s.x += bv.x; s.y += bv.y; s.z += bv.z; s.w += bv.w;
    if (act == 1) {
        s.x = fmaxf(s.x, 0.0f); s.y = fmaxf(s.y, 0.0f);
        s.z = fmaxf(s.z, 0.0f); s.w = fmaxf(s.w, 0.0f);
    } else if (act == 2) {
        s.x = tanhf(s.x); s.y = tanhf(s.y); s.z = tanhf(s.z); s.w = tanhf(s.w);
    }
    *reinterpret_cast<float4*>(&Y[i4]) = s;
}

// ---------------- scores: one warp per l, grid (B, 25) -----------------------
__global__ void __launch_bounds__(256) score_kernel(const float* __restrict__ cfe,
                                                    const float* __restrict__ W_a,
                                                    const float* __restrict__ b_a)
{
    __shared__ __align__(16) float s_hoe[DD];
    __shared__ __align__(16) float s_wa[DD];

    const int b   = blockIdx.x;
    const int tid = threadIdx.x;
    for (int i = tid; i < DD; i += 256) {
        s_hoe[i] = g_ho_e[b * DD + i];
        s_wa[i]  = W_a[i];
    }
    __syncthreads();

    const int warp = tid >> 5;
    const int lane = tid & 31;
    const int l = blockIdx.y * 8 + warp;
    if (l >= LP1) return;

    const float* ebase = (l == 0) ? (g_fr_e + (size_t)b * DD)
                                  : (cfe + ((size_t)b * LL + (l - 1)) * (size_t)DD);
    float acc = 0.0f;
#pragma unroll
    for (int i = 0; i < 8; ++i) {
        int d = i * 128 + lane * 4;
        float4 e = *reinterpret_cast<const float4*>(ebase + d);
        float4 h = *reinterpret_cast<const float4*>(&s_hoe[d]);
        float4 a = *reinterpret_cast<const float4*>(&s_wa[d]);
        acc = fmaf(fast_tanh(e.x + h.x), a.x, acc);
        acc = fmaf(fast_tanh(e.y + h.y), a.y, acc);
        acc = fmaf(fast_tanh(e.z + h.z), a.z, acc);
        acc = fmaf(fast_tanh(e.w + h.w), a.w, acc);
    }
#pragma unroll
    for (int off = 16; off > 0; off >>= 1)
        acc += __shfl_down_sync(0xffffffffu, acc, off);
    if (lane == 0) g_scores[b * LP1 + l] = acc + b_a[0];
}

// ---------------- softmax over 197 scores, one CTA per b ---------------------
__global__ void softmax_kernel()
{
    __shared__ float s_red[8];
    const int b   = blockIdx.x;
    const int tid = threadIdx.x;
    const int warp = tid >> 5, lane = tid & 31;

    float v = (tid < LP1) ? g_scores[b * LP1 + tid] : -1e30f;
    float m = v;
#pragma unroll
    for (int off = 16; off > 0; off >>= 1)
        m = fmaxf(m, __shfl_xor_sync(0xffffffffu, m, off));
    if (lane == 0) s_red[warp] = m;
    __syncthreads();
    if (tid == 0) {
        float mm = s_red[0];
#pragma unroll
        for (int i = 1; i < 8; i++) mm = fmaxf(mm, s_red[i]);
        s_red[0] = mm;
    }
    __syncthreads();
    const float mx = s_red[0];
    float pv = (tid < LP1) ? expf(v - mx) : 0.0f;
    float ssum = pv;
#pragma unroll
    for (int off = 16; off > 0; off >>= 1)
        ssum += __shfl_xor_sync(0xffffffffu, ssum, off);
    __syncthreads();
    if (lane == 0) s_red[warp] = ssum;
    __syncthreads();
    if (tid == 0) {
        float tsum = 0.0f;
#pragma unroll
        for (int i = 0; i < 8; i++) tsum += s_red[i];
        s_red[0] = tsum;
    }
    __syncthreads();
    const float inv = 1.0f / s_red[0];
    if (tid < LP1) g_PI[b * LP1 + tid] = pv * inv;
}

// ---------------- weighted sum, split-L partials -----------------------------
__global__ void __launch_bounds__(128) wsum_part_kernel(const float* __restrict__ conv_feat)
{
    __shared__ float s_pi[WCH];
    const int b = blockIdx.y;
    const int s = blockIdx.z;
    const int d = blockIdx.x * 512 + threadIdx.x * 4;
    const int l0 = s * WCH;

    for (int i = threadIdx.x; i < WCH; i += 128)
        s_pi[i] = g_PI[b * LP1 + 1 + l0 + i];
    __syncthreads();

    float4 acc;
    if (s == 0) {
        const float p0 = g_PI[b * LP1];
        float4 fr4 = *reinterpret_cast<const float4*>(&g_fr[b * DD + d]);
        float4 ho4 = *reinterpret_cast<const float4*>(&g_ho[b * DD + d]);
        acc.x = fmaf(p0, fr4.x, ho4.x);
        acc.y = fmaf(p0, fr4.y, ho4.y);
        acc.z = fmaf(p0, fr4.z, ho4.z);
        acc.w = fmaf(p0, fr4.w, ho4.w);
    } else {
        acc = make_float4(0.0f, 0.0f, 0.0f, 0.0f);
    }

    const float* cf = conv_feat + ((size_t)b * LL + l0) * DD + d;
#pragma unroll 7
    for (int l = 0; l < WCH; ++l) {
        float4 v = *reinterpret_cast<const float4*>(cf + (size_t)l * DD);
        float p = s_pi[l];
        acc.x = fmaf(p, v.x, acc.x);
        acc.y = fmaf(p, v.y, acc.y);
        acc.z = fmaf(p, v.z, acc.z);
        acc.w = fmaf(p, v.w, acc.w);
    }
    *reinterpret_cast<float4*>(&g_wpart[s][b * DD + d]) = acc;
}

__global__ void __launch_bounds__(256) wsum_red_kernel()
{
    const int i4 = (blockIdx.x * 256 + threadIdx.x) * 4;
    float4 a = *reinterpret_cast<const float4*>(&g_wpart[0][i4]);
    float4 c = *reinterpret_cast<const float4*>(&g_wpart[1][i4]);
    a.x += c.x; a.y += c.y; a.z += c.z; a.w += c.w;
    *reinterpret_cast<float4*>(&g_att[i4]) = a;
}

// ---------------- launch -----------------------------------------------------
extern "C" void kernel_launch(void* const* d_in, const int* in_sizes, int n_in,
                              void* d_out, int out_size)
{
    const float* h_out       = (const float*)d_in[0];
    const float* fake_region = (const float*)d_in[1];
    const float* conv_feat   = (const float*)d_in[2];
    const float* conv_embed  = (const float*)d_in[3];
    const float* W_fr  = (const float*)d_in[4];
    const float* b_fr  = (const float*)d_in[5];
    const float* W_fre = (const float*)d_in[6];
    const float* b_fre = (const float*)d_in[7];
    const float* W_ho  = (const float*)d_in[8];
    const float* b_ho  = (const float*)d_in[9];
    const float* W_hoe = (const float*)d_in[10];
    const float* b_hoe = (const float*)d_in[11];
    const float* W_a   = (const float*)d_in[12];
    const float* b_a   = (const float*)d_in[13];
    const float* W_h   = (const float*)d_in[14];
    const float* b_h   = (const float*)d_in[15];
    float* out = (float*)d_out;

    float *p_fr, *p_ho, *p_fr_e, *p_ho_e, *p_att;
    cudaGetSymbolAddress((void**)&p_fr,   g_fr);
    cudaGetSymbolAddress((void**)&p_ho,   g_ho);
    cudaGetSymbolAddress((void**)&p_fr_e, g_fr_e);
    cudaGetSymbolAddress((void**)&p_ho_e, g_ho_e);
    cudaGetSymbolAddress((void**)&p_att,  g_att);

    const dim3 gg2(DD / GBN, (BB / GBM) * SPLITK, 2);   // 16 x 8 x 2 = 256 CTAs
    const dim3 gg1(DD / GBN, (BB / GBM) * SPLITK, 1);
    const dim3 ge2(BB * DD / 1024, 2);                  // 128 x 2
    const dim3 ge1(BB * DD / 1024, 1);

    // stage 1: fr = relu(fake_region@W_fr^T+b), ho = tanh(h_out@W_ho^T+b)
    gemm_tf32_kernel<<<gg2, 256>>>(fake_region, W_fr, h_out, W_ho);
    epi_kernel<<<ge2, 256>>>(p_fr, b_fr, 1, p_ho, b_ho, 2);
    // stage 2: fr_e, ho_e (no activation)
    gemm_tf32_kernel<<<gg2, 256>>>(p_fr, W_fre, p_ho, W_hoe);
    epi_kernel<<<ge2, 256>>>(p_fr_e, b_fre, 0, p_ho_e, b_hoe, 0);
    // attention scores + softmax
    score_kernel<<<dim3(BB, 25), 256>>>(conv_embed, W_a, b_a);
    softmax_kernel<<<BB, 256>>>();
    // visAtt + ho (split-L partials + reduce)
    wsum_part_kernel<<<dim3(2, BB, WSPL), 128>>>(conv_feat);
    wsum_red_kernel<<<BB * DD / 1024, 256>>>();
    // stage 3: h = tanh(att@W_h^T + b_h)
    gemm_tf32_kernel<<<gg1, 256>>>(p_att, W_h, p_att, W_h);
    epi_kernel<<<ge1, 256>>>(out, b_h, 2, out, b_h, 2);
}